// round 3
// baseline (speedup 1.0000x reference)
#include <cuda_runtime.h>

#define N    4096
#define K    10          // fused Jacobi steps per pass
#define TX   108         // output tile edge (TX + 2K = 128)
#define BW   128         // smem buffer edge
#define NBLK 38          // ceil(4096 / 108)
#define NTH  1024

// Scratch ping-pong buffer (allocation-free rule: __device__ global).
__device__ float g_buf[(size_t)N * N];

__global__ void init_kernel(const float* __restrict__ X,
                            const float* __restrict__ Y,
                            float* __restrict__ out) {
    int i = blockIdx.x * blockDim.x + threadIdx.x;
    float dx = X[i] - 0.5f;
    float dy = Y[i] - 0.5f;
    out[i] = __expf(-50.0f * (dx * dx + dy * dy));
}

__global__ __launch_bounds__(NTH, 1)
void jacobi_pass(const float* __restrict__ in, float* __restrict__ out) {
    extern __shared__ float smem[];
    float* b0 = smem;
    float* b1 = smem + BW * BW;

    const int tid = threadIdx.x;
    const int gx0 = blockIdx.x * TX - K;
    const int gy0 = blockIdx.y * TX - K;

    // ---- load 128x128 tile (zero-fill outside domain) ----
    for (int i = tid; i < BW * BW; i += NTH) {
        int x = i & (BW - 1);
        int y = i >> 7;
        int gx = gx0 + x, gy = gy0 + y;
        float v = 0.0f;
        if (gx >= 0 && gx < N && gy >= 0 && gy < N)
            v = in[(size_t)gy * N + gx];
        b0[i] = v;
    }
    __syncthreads();

    const int lane = tid & 31;
    const int warp = tid >> 5;          // 0..31
    const int x4   = lane * 4;          // float4 column, covers x 0..127

    // rows 1..126 split across 32 warps, 4 rows each (last warp: 2)
    const int y_beg = 1 + warp * 4;
    const int y_end = min(y_beg + 4, BW - 1);   // exclusive

    // does this tile's full 128x128 patch lie strictly inside the domain
    // interior [1, N-2]^2?  If yes -> no masks needed anywhere.
    const bool tile_interior =
        (gx0 >= 1) && (gx0 + BW - 1 <= N - 2) &&
        (gy0 >= 1) && (gy0 + BW - 1 <= N - 2);

    if (tile_interior) {
        // ---- fast path: branchless, no masks ----
        for (int s = 0; s < K; s++) {
            const float* src = (s & 1) ? b1 : b0;
            float*       dst = (s & 1) ? b0 : b1;

            float4 up  = *(const float4*)(src + (y_beg - 1) * BW + x4);
            float4 cur = *(const float4*)(src + (y_beg    ) * BW + x4);

            #pragma unroll
            for (int r = 0; r < 4; r++) {
                int y = y_beg + r;
                if (y >= y_end) break;
                float4 dn = *(const float4*)(src + (y + 1) * BW + x4);
                float lf = __shfl_up_sync(0xffffffffu, cur.w, 1);
                float rt = __shfl_down_sync(0xffffffffu, cur.x, 1);

                float4 o;
                o.x = 0.25f * (lf    + cur.y + up.x + dn.x);
                o.y = 0.25f * (cur.x + cur.z + up.y + dn.y);
                o.z = 0.25f * (cur.y + cur.w + up.z + dn.z);
                o.w = 0.25f * (cur.z + rt    + up.w + dn.w);
                *(float4*)(dst + y * BW + x4) = o;

                up = cur; cur = dn;
            }
            __syncthreads();
        }
    } else {
        // ---- edge path: per-cell domain-interior masks ----
        const int gxb = gx0 + x4;
        const bool xin0 = (gxb + 0 >= 1) && (gxb + 0 <= N - 2);
        const bool xin1 = (gxb + 1 >= 1) && (gxb + 1 <= N - 2);
        const bool xin2 = (gxb + 2 >= 1) && (gxb + 2 <= N - 2);
        const bool xin3 = (gxb + 3 >= 1) && (gxb + 3 <= N - 2);

        for (int s = 0; s < K; s++) {
            const float* src = (s & 1) ? b1 : b0;
            float*       dst = (s & 1) ? b0 : b1;

            float4 up  = *(const float4*)(src + (y_beg - 1) * BW + x4);
            float4 cur = *(const float4*)(src + (y_beg    ) * BW + x4);

            for (int y = y_beg; y < y_end; y++) {
                float4 dn = *(const float4*)(src + (y + 1) * BW + x4);
                float lf = __shfl_up_sync(0xffffffffu, cur.w, 1);
                float rt = __shfl_down_sync(0xffffffffu, cur.x, 1);

                int  gy  = gy0 + y;
                bool yin = (gy >= 1) && (gy <= N - 2);

                float4 o;
                o.x = (yin && xin0) ? 0.25f * (lf    + cur.y + up.x + dn.x) : 0.0f;
                o.y = (yin && xin1) ? 0.25f * (cur.x + cur.z + up.y + dn.y) : 0.0f;
                o.z = (yin && xin2) ? 0.25f * (cur.y + cur.w + up.z + dn.z) : 0.0f;
                o.w = (yin && xin3) ? 0.25f * (cur.z + rt    + up.w + dn.w) : 0.0f;
                *(float4*)(dst + y * BW + x4) = o;

                up = cur; cur = dn;
            }
            __syncthreads();
        }
    }

    // ---- write valid center TX x TX (final state in b0 since K is even) ----
    for (int y = K + warp; y <= BW - 1 - K; y += 32) {
        int gy = gy0 + y;
        if (gy >= N) continue;
        for (int x = K + lane; x <= BW - 1 - K; x += 32) {
            int gx = gx0 + x;
            if (gx < N)
                out[(size_t)gy * N + gx] = b0[y * BW + x];
        }
    }
}

extern "C" void kernel_launch(void* const* d_in, const int* in_sizes, int n_in,
                              void* d_out, int out_size) {
    const float* X = (const float*)d_in[0];
    const float* Y = (const float*)d_in[1];
    float* A = (float*)d_out;
    float* B;
    cudaGetSymbolAddress((void**)&B, g_buf);

    const int smem_bytes = 2 * BW * BW * (int)sizeof(float);   // 131072
    cudaFuncSetAttribute(jacobi_pass,
                         cudaFuncAttributeMaxDynamicSharedMemorySize, smem_bytes);

    // init: x0 -> A
    init_kernel<<<(N * N) / 256, 256>>>(X, Y, A);

    // 10 passes of K=10 fused steps each; 10 even -> final lands in A (=d_out)
    dim3 grid(NBLK, NBLK);
    for (int p = 0; p < 100 / K; p++) {
        const float* src = (p % 2 == 0) ? A : B;
        float*       dst = (p % 2 == 0) ? B : A;
        jacobi_pass<<<grid, NTH, smem_bytes>>>(src, dst);
    }
}

// round 4
// speedup vs baseline: 2.5717x; 2.5717x over previous
#include <cuda_runtime.h>

#define N    4096
#define K    10          // fused Jacobi steps per pass
#define TX   108         // output tile edge (TX + 2K = 128)
#define BW   128         // tile edge (width & height)
#define NBLK 38          // ceil(4096 / 108)
#define NTH  512
#define NW   16          // warps per CTA
#define R    8           // rows per warp (NW * R == BW)

// Scratch ping-pong buffer (allocation-free rule: __device__ global).
__device__ float g_buf[(size_t)N * N];

__global__ void init_kernel(const float* __restrict__ X,
                            const float* __restrict__ Y,
                            float* __restrict__ out) {
    int i = blockIdx.x * blockDim.x + threadIdx.x;
    float dx = X[i] - 0.5f;
    float dy = Y[i] - 0.5f;
    out[i] = __expf(-50.0f * (dx * dx + dy * dy));
}

// Exchange buffer type: [step parity][top=0/bot=1][warp][col]
typedef float ExBuf[2][NW][BW];

template<bool EDGE>
__device__ __forceinline__ void run_steps(float4 (&u)[R], ExBuf* ex,
                                          int warp, int x4,
                                          int gx0, int gy0, int ybase) {
    float mx0 = 1.f, mx1 = 1.f, mx2 = 1.f, mx3 = 1.f;
    if (EDGE) {
        int g = gx0 + x4;
        mx0 = (g + 0 >= 1 && g + 0 <= N - 2) ? 1.f : 0.f;
        mx1 = (g + 1 >= 1 && g + 1 <= N - 2) ? 1.f : 0.f;
        mx2 = (g + 2 >= 1 && g + 2 <= N - 2) ? 1.f : 0.f;
        mx3 = (g + 3 >= 1 && g + 3 <= N - 2) ? 1.f : 0.f;
    }

    #pragma unroll 2
    for (int s = 0; s < K; s++) {
        const int par = s & 1;

        // publish own boundary rows (old values) for neighbor warps
        *(float4*)&ex[par][0][warp][x4] = u[0];       // my top row
        *(float4*)&ex[par][1][warp][x4] = u[R - 1];   // my bottom row
        __syncthreads();

        float4 above = make_float4(0.f, 0.f, 0.f, 0.f);
        if (warp > 0)
            above = *(const float4*)&ex[par][1][warp - 1][x4];
        float4 bedge = make_float4(0.f, 0.f, 0.f, 0.f);
        if (warp < NW - 1)
            bedge = *(const float4*)&ex[par][0][warp + 1][x4];

        #pragma unroll
        for (int r = 0; r < R; r++) {
            float4 cur = u[r];
            float4 dn  = (r < R - 1) ? u[r + 1] : bedge;
            float lf = __shfl_up_sync(0xffffffffu, cur.w, 1);
            float rt = __shfl_down_sync(0xffffffffu, cur.x, 1);

            float4 nv;
            nv.x = __fmaf_rn(lf,    0.25f, __fmaf_rn(cur.y, 0.25f,
                   __fmaf_rn(above.x, 0.25f, dn.x * 0.25f)));
            nv.y = __fmaf_rn(cur.x, 0.25f, __fmaf_rn(cur.z, 0.25f,
                   __fmaf_rn(above.y, 0.25f, dn.y * 0.25f)));
            nv.z = __fmaf_rn(cur.y, 0.25f, __fmaf_rn(cur.w, 0.25f,
                   __fmaf_rn(above.z, 0.25f, dn.z * 0.25f)));
            nv.w = __fmaf_rn(cur.z, 0.25f, __fmaf_rn(rt,    0.25f,
                   __fmaf_rn(above.w, 0.25f, dn.w * 0.25f)));

            if (EDGE) {
                int gy = gy0 + ybase + r;
                float my = (gy >= 1 && gy <= N - 2) ? 1.f : 0.f;
                nv.x *= my * mx0; nv.y *= my * mx1;
                nv.z *= my * mx2; nv.w *= my * mx3;
            }

            u[r]  = nv;
            above = cur;   // old value of this row feeds the next row
        }
        // single barrier per step: exchange slots are double-buffered by
        // parity, and the next overwrite of this parity's slots happens
        // only after the NEXT step's barrier.
    }
}

__global__ __launch_bounds__(NTH, 2)
void jacobi_pass(const float* __restrict__ in, float* __restrict__ out) {
    __shared__ ExBuf ex[2];   // 2 * 2 * 16 * 128 * 4B = 32 KB

    const int tid   = threadIdx.x;
    const int lane  = tid & 31;
    const int warp  = tid >> 5;
    const int x4    = lane * 4;
    const int gx0   = blockIdx.x * TX - K;
    const int gy0   = blockIdx.y * TX - K;
    const int ybase = warp * R;

    const bool tile_interior =
        (gx0 >= 1) && (gx0 + BW - 1 <= N - 2) &&
        (gy0 >= 1) && (gy0 + BW - 1 <= N - 2);

    float4 u[R];

    // ---- load 8 rows x 4 cols straight into registers ----
    if (tile_interior) {
        #pragma unroll
        for (int r = 0; r < R; r++) {
            const float* p = in + (size_t)(gy0 + ybase + r) * N + gx0 + x4;
            u[r].x = p[0]; u[r].y = p[1]; u[r].z = p[2]; u[r].w = p[3];
        }
    } else {
        #pragma unroll
        for (int r = 0; r < R; r++) {
            int gy = gy0 + ybase + r;
            float4 v = make_float4(0.f, 0.f, 0.f, 0.f);
            if (gy >= 0 && gy < N) {
                const float* row = in + (size_t)gy * N;
                int g = gx0 + x4;
                if (g + 0 >= 0 && g + 0 < N) v.x = row[g + 0];
                if (g + 1 >= 0 && g + 1 < N) v.y = row[g + 1];
                if (g + 2 >= 0 && g + 2 < N) v.z = row[g + 2];
                if (g + 3 >= 0 && g + 3 < N) v.w = row[g + 3];
            }
            u[r] = v;
        }
    }

    // ---- K fused Jacobi steps, state in registers ----
    if (tile_interior)
        run_steps<false>(u, ex, warp, x4, gx0, gy0, ybase);
    else
        run_steps<true>(u, ex, warp, x4, gx0, gy0, ybase);

    // ---- write valid center [K, BW-1-K]^2 ----
    #pragma unroll
    for (int r = 0; r < R; r++) {
        int ty = ybase + r;
        if (ty < K || ty > BW - 1 - K) continue;
        int gy = gy0 + ty;
        if (gy >= N) continue;               // gy >= 0 guaranteed (ty >= K)
        float* row = out + (size_t)gy * N;
        int g = gx0 + x4;
        if (x4 + 0 >= K && x4 + 0 <= BW - 1 - K && g + 0 < N) row[g + 0] = u[r].x;
        if (x4 + 1 >= K && x4 + 1 <= BW - 1 - K && g + 1 < N) row[g + 1] = u[r].y;
        if (x4 + 2 >= K && x4 + 2 <= BW - 1 - K && g + 2 < N) row[g + 2] = u[r].z;
        if (x4 + 3 >= K && x4 + 3 <= BW - 1 - K && g + 3 < N) row[g + 3] = u[r].w;
    }
}

extern "C" void kernel_launch(void* const* d_in, const int* in_sizes, int n_in,
                              void* d_out, int out_size) {
    const float* X = (const float*)d_in[0];
    const float* Y = (const float*)d_in[1];
    float* A = (float*)d_out;
    float* B;
    cudaGetSymbolAddress((void**)&B, g_buf);

    // init: x0 -> A
    init_kernel<<<(N * N) / 256, 256>>>(X, Y, A);

    // 10 passes of K=10 fused steps each; 10 even -> final lands in A (=d_out)
    dim3 grid(NBLK, NBLK);
    for (int p = 0; p < 100 / K; p++) {
        const float* src = (p % 2 == 0) ? A : B;
        float*       dst = (p % 2 == 0) ? B : A;
        jacobi_pass<<<grid, NTH>>>(src, dst);
    }
}